// round 10
// baseline (speedup 1.0000x reference)
#include <cuda_runtime.h>
#include <cstdint>

// Problem constants
#define BB 8
#define TT 200
#define UU 100
#define EE 512
#define PP 640
#define HH 512
#define VV 1024
#define TUU (TT * UU)          // 20000
#define MTOT (BB * TUU)        // 160000

// Scratch (no cudaMalloc allowed)
__device__ float g_enc[BB * TT * HH];   // 1600 x 512
__device__ float g_pred[BB * UU * HH];  //  800 x 512

// ===========================================================================
// Helpers
// ===========================================================================
__device__ __forceinline__ uint32_t smem_u32(const void* p) {
    uint32_t a;
    asm("{ .reg .u64 t; cvta.to.shared.u64 t, %1; cvt.u32.u64 %0, t; }"
        : "=r"(a) : "l"(p));
    return a;
}

__device__ __forceinline__ unsigned f2tf32(float x) {
    unsigned r;
    asm("cvt.rna.tf32.f32 %0, %1;" : "=r"(r) : "f"(x));
    return r;
}

__device__ __forceinline__ void mma_tf32(float* c, const unsigned* a,
                                         unsigned b0, unsigned b1) {
    asm volatile(
        "mma.sync.aligned.m16n8k8.row.col.f32.tf32.tf32.f32 "
        "{%0,%1,%2,%3}, {%4,%5,%6,%7}, {%8,%9}, {%0,%1,%2,%3};\n"
        : "+f"(c[0]), "+f"(c[1]), "+f"(c[2]), "+f"(c[3])
        : "r"(a[0]), "r"(a[1]), "r"(a[2]), "r"(a[3]), "r"(b0), "r"(b1));
}

__device__ __forceinline__ void cp_async16(uint32_t dst, const void* src) {
    asm volatile(
        "{ .reg .u64 g; cvta.to.global.u64 g, %1;"
        "  cp.async.cg.shared.global [%0], [g], 16; }"
        :: "r"(dst), "l"(src) : "memory");
}
#define CP_COMMIT() asm volatile("cp.async.commit_group;" ::: "memory")
#define CP_WAIT0()  asm volatile("cp.async.wait_group 0;" ::: "memory")

// ===========================================================================
// Phase 1: both projections in one launch (z=0: enc, z=1: pred)
// ===========================================================================
__global__ __launch_bounds__(256) void proj_both_kernel(
    const float* __restrict__ encX, const float* __restrict__ Wenc,
    const float* __restrict__ benc, float* __restrict__ encY,
    const float* __restrict__ predX, const float* __restrict__ Wpred,
    const float* __restrict__ bpred, float* __restrict__ predY)
{
    const int z = blockIdx.z;
    const float* X = z ? predX : encX;
    const float* W = z ? Wpred : Wenc;
    const float* bias = z ? bpred : benc;
    float* Y = z ? predY : encY;
    const int M = z ? (BB * UU) : (BB * TT);
    const int K = z ? PP : EE;
    const int N = HH;

    const int mBase = blockIdx.y * 64;
    if (mBase >= M) return;
    const int nBase = blockIdx.x * 64;

    __shared__ float Xs[16][68];
    __shared__ float Ws[16][68];

    const int tx = threadIdx.x;
    const int ty = threadIdx.y;
    const int tid = ty * 16 + tx;
    const int lm = tid & 63;
    const int kq = (tid >> 6) * 4;

    float acc[4][4];
#pragma unroll
    for (int i = 0; i < 4; i++)
#pragma unroll
        for (int j = 0; j < 4; j++) acc[i][j] = 0.f;

    for (int k0 = 0; k0 < K; k0 += 16) {
        float4 xv = make_float4(0.f, 0.f, 0.f, 0.f);
        const int row = mBase + lm;
        if (row < M)
            xv = *(const float4*)(X + (size_t)row * K + k0 + kq);
        Xs[kq + 0][lm] = xv.x; Xs[kq + 1][lm] = xv.y;
        Xs[kq + 2][lm] = xv.z; Xs[kq + 3][lm] = xv.w;

        float4 wv = *(const float4*)(W + (size_t)(nBase + lm) * K + k0 + kq);
        Ws[kq + 0][lm] = wv.x; Ws[kq + 1][lm] = wv.y;
        Ws[kq + 2][lm] = wv.z; Ws[kq + 3][lm] = wv.w;

        __syncthreads();
#pragma unroll
        for (int kk = 0; kk < 16; kk++) {
            float4 a = *(const float4*)&Xs[kk][ty * 4];
            float4 b = *(const float4*)&Ws[kk][tx * 4];
            float av[4] = {a.x, a.y, a.z, a.w};
            float bv[4] = {b.x, b.y, b.z, b.w};
#pragma unroll
            for (int i = 0; i < 4; i++)
#pragma unroll
                for (int j = 0; j < 4; j++)
                    acc[i][j] = fmaf(av[i], bv[j], acc[i][j]);
        }
        __syncthreads();
    }

    float4 bb = *(const float4*)(bias + nBase + tx * 4);
    float bv[4] = {bb.x, bb.y, bb.z, bb.w};
#pragma unroll
    for (int i = 0; i < 4; i++) {
        const int row = mBase + ty * 4 + i;
        if (row < M) {
            float4 o;
            o.x = acc[i][0] + bv[0]; o.y = acc[i][1] + bv[1];
            o.z = acc[i][2] + bv[2]; o.w = acc[i][3] + bv[3];
            *(float4*)(Y + (size_t)row * N + nBase + tx * 4) = o;
        }
    }
}

// ===========================================================================
// Phase 2: fused joint GEMM, tf32 mma.sync, double-buffered.
//   CTA 128(M) x 256(N), K-chunk 32, 512 threads, warp tile 64x32.
//   A = relu(enc+pred): generated -> fragment-ordered xor-swizzled smem
//   B = W_out: cp.async -> per-row xor-swizzled k-major smem
// ===========================================================================
#define JOFF_PRED 512
#define JOFF_A    1024
#define JOFF_B    33792
#define JSMEM_TOT (99328 + 1024)

__global__ __launch_bounds__(512, 1) void joint_mma_kernel(
    const float* __restrict__ Wout, const float* __restrict__ bout,
    float* __restrict__ out)
{
    extern __shared__ char smem_raw[];
    char* sm = smem_raw + ((1024u - (smem_u32(smem_raw) & 1023u)) & 1023u);
    const uint32_t sb = smem_u32(sm);

    const int tid = threadIdx.x;
    const int wrp = tid >> 5;
    const int lane = tid & 31;
    const int mBase = blockIdx.x * 128;
    const int vBase = blockIdx.y * 256;

    int* encOffS = (int*)sm;
    int* predOffS = (int*)(sm + JOFF_PRED);

    if (tid < 128) {
        const int gm = mBase + tid;
        const int b = gm / TUU;
        const int r = gm % TUU;
        const int t = r / UU;
        const int u = r % UU;
        encOffS[tid] = (b * TT + t) * HH;
        predOffS[tid] = (b * UU + u) * HH;
    }
    __syncthreads();

    // ---- A-generator mapping: thread -> (row, k-octet) ----
    const int ar = tid & 127;            // m-row in tile
    const int ao = tid >> 7;             // k-step index 0..3
    const int aEnc = encOffS[ar];
    const int aPred = predOffS[ar];
    const int aGrpBase = ((ar >> 4) * 4 + ao) * 32;   // fragment group * 32
    const int aLbase = (ar & 7) * 4;                  // lane-entry base
    const int aHalf = ((ar >> 3) & 1) * 8;            // byte half within entry

    // ---- B loader mapping: thread -> half W_out row ----
    const int bn = tid >> 1;             // 0..255
    const int bj0 = (tid & 1) * 4;       // granule base 0 or 4
    const float* bsrc = Wout + (size_t)(vBase + bn) * HH;
    const uint32_t bRow = (uint32_t)bn * 128;
    const uint32_t bXor = (uint32_t)(bn & 7) * 16;

    // ---- MMA mapping ----
    const int wm = wrp >> 3;             // 0..1 (M)
    const int wn = wrp & 7;              // 0..7 (N)
    const int gID = lane >> 2;
    const int t4 = lane & 3;

    float acc[4][4][4];
#pragma unroll
    for (int f = 0; f < 4; f++)
#pragma unroll
        for (int j = 0; j < 4; j++)
#pragma unroll
            for (int c = 0; c < 4; c++) acc[f][j][c] = 0.f;

#define GEN_A(stageBase, K0) do {                                             \
    const float* ep = g_enc + aEnc + (K0) + ao * 8;                           \
    const float* pp = g_pred + aPred + (K0) + ao * 8;                         \
    float4 e0 = *(const float4*)(ep);                                         \
    float4 e1 = *(const float4*)(ep + 4);                                     \
    float4 p0 = *(const float4*)(pp);                                         \
    float4 p1 = *(const float4*)(pp + 4);                                     \
    unsigned v[8];                                                            \
    v[0] = f2tf32(fmaxf(e0.x + p0.x, 0.f));                                   \
    v[1] = f2tf32(fmaxf(e0.y + p0.y, 0.f));                                   \
    v[2] = f2tf32(fmaxf(e0.z + p0.z, 0.f));                                   \
    v[3] = f2tf32(fmaxf(e0.w + p0.w, 0.f));                                   \
    v[4] = f2tf32(fmaxf(e1.x + p1.x, 0.f));                                   \
    v[5] = f2tf32(fmaxf(e1.y + p1.y, 0.f));                                   \
    v[6] = f2tf32(fmaxf(e1.z + p1.z, 0.f));                                   \
    v[7] = f2tf32(fmaxf(e1.w + p1.w, 0.f));                                   \
    _Pragma("unroll")                                                         \
    for (int q = 0; q < 4; q++) {                                             \
        uint32_t ef = (uint32_t)(aGrpBase + aLbase + q);                      \
        uint32_t es = ef ^ ((ef >> 3) & 7u);                                  \
        uint2 pr; pr.x = v[q]; pr.y = v[q + 4];                               \
        *(uint2*)(sm + (stageBase) + es * 16 + aHalf) = pr;                   \
    }                                                                         \
} while (0)

#define LOAD_B(stageBase, K0) do {                                            \
    _Pragma("unroll")                                                         \
    for (int jj = 0; jj < 4; jj++) {                                          \
        const int jg = bj0 + jj;                                              \
        cp_async16(sb + (stageBase) + bRow + (((uint32_t)jg * 16) ^ bXor),    \
                   bsrc + (K0) + jg * 4);                                     \
    }                                                                         \
} while (0)

    // ---- prologue: fill stage 0 ----
    GEN_A(JOFF_A, 0);
    LOAD_B(JOFF_B, 0);
    CP_COMMIT();
    CP_WAIT0();
    __syncthreads();

    // ---- main loop: 16 chunks of K=32 ----
    for (int it = 0; it < 16; it++) {
        const int cur = it & 1;
        const int nxt = cur ^ 1;
        const uint32_t aCur = JOFF_A + cur * 16384;
        const uint32_t bCur = JOFF_B + cur * 32768;

        // prefetch next chunk (A: LDG into regs; B: cp.async)
        float4 e0, e1, p0, p1;
        if (it < 15) {
            const int k0n = (it + 1) * 32;
            const float* ep = g_enc + aEnc + k0n + ao * 8;
            const float* pp = g_pred + aPred + k0n + ao * 8;
            e0 = *(const float4*)(ep);
            e1 = *(const float4*)(ep + 4);
            p0 = *(const float4*)(pp);
            p1 = *(const float4*)(pp + 4);
            LOAD_B(JOFF_B + nxt * 32768, k0n);
            CP_COMMIT();
        }

        // MMAs on current stage
#pragma unroll
        for (int ks = 0; ks < 4; ks++) {
            unsigned a[4][4];
#pragma unroll
            for (int f = 0; f < 4; f++) {
                uint32_t ef = (uint32_t)((((wm * 4 + f) * 4 + ks) * 32) + lane);
                uint32_t es = ef ^ ((ef >> 3) & 7u);
                unsigned x, y, z, w;
                asm volatile("ld.shared.v4.b32 {%0,%1,%2,%3}, [%4];"
                             : "=r"(x), "=r"(y), "=r"(z), "=r"(w)
                             : "r"(sb + aCur + es * 16));
                a[f][0] = x; a[f][1] = z; a[f][2] = y; a[f][3] = w;
            }
#pragma unroll
            for (int j = 0; j < 4; j++) {
                const int n = wn * 32 + j * 8 + gID;
                const uint32_t rowBase = sb + bCur + (uint32_t)n * 128;
                const uint32_t nx = (uint32_t)(n & 7) * 16;
                const uint32_t off0 = (uint32_t)(ks * 32 + t4 * 4);
                // FIX: apply XOR swizzle to each k-granule offset separately
                unsigned b0, b1;
                asm volatile("ld.shared.b32 %0, [%1];" : "=r"(b0)
                             : "r"(rowBase + (off0 ^ nx)));
                asm volatile("ld.shared.b32 %0, [%1];" : "=r"(b1)
                             : "r"(rowBase + ((off0 + 16) ^ nx)));
#pragma unroll
                for (int f = 0; f < 4; f++)
                    mma_tf32(acc[f][j], a[f], b0, b1);
            }
        }

        // finish next-stage A (relu+convert+STS) and drain cp.async
        if (it < 15) {
            unsigned v[8];
            v[0] = f2tf32(fmaxf(e0.x + p0.x, 0.f));
            v[1] = f2tf32(fmaxf(e0.y + p0.y, 0.f));
            v[2] = f2tf32(fmaxf(e0.z + p0.z, 0.f));
            v[3] = f2tf32(fmaxf(e0.w + p0.w, 0.f));
            v[4] = f2tf32(fmaxf(e1.x + p1.x, 0.f));
            v[5] = f2tf32(fmaxf(e1.y + p1.y, 0.f));
            v[6] = f2tf32(fmaxf(e1.z + p1.z, 0.f));
            v[7] = f2tf32(fmaxf(e1.w + p1.w, 0.f));
            const uint32_t aNxt = JOFF_A + nxt * 16384;
#pragma unroll
            for (int q = 0; q < 4; q++) {
                uint32_t ef = (uint32_t)(aGrpBase + aLbase + q);
                uint32_t es = ef ^ ((ef >> 3) & 7u);
                uint2 pr; pr.x = v[q]; pr.y = v[q + 4];
                *(uint2*)(sm + aNxt + es * 16 + aHalf) = pr;
            }
            CP_WAIT0();
        }
        __syncthreads();
    }

    // ---- epilogue: (acc + b_out) * 0.1 ----
#pragma unroll
    for (int f = 0; f < 4; f++) {
        const int row0 = mBase + wm * 64 + f * 16 + gID;
#pragma unroll
        for (int j = 0; j < 4; j++) {
            const int col = vBase + wn * 32 + j * 8 + t4 * 2;
            const float2 bv = *(const float2*)(bout + col);
            float2 r0, r1;
            r0.x = (acc[f][j][0] + bv.x) * 0.1f;
            r0.y = (acc[f][j][1] + bv.y) * 0.1f;
            r1.x = (acc[f][j][2] + bv.x) * 0.1f;
            r1.y = (acc[f][j][3] + bv.y) * 0.1f;
            *(float2*)(out + (size_t)row0 * VV + col) = r0;
            *(float2*)(out + (size_t)(row0 + 8) * VV + col) = r1;
        }
    }
}

// ===========================================================================
// Launch
// ===========================================================================
extern "C" void kernel_launch(void* const* d_in, const int* in_sizes, int n_in,
                              void* d_out, int out_size)
{
    (void)in_sizes; (void)n_in; (void)out_size;
    const float* enc_in  = (const float*)d_in[0];
    const float* pred_in = (const float*)d_in[1];
    const float* W_enc   = (const float*)d_in[2];
    const float* b_enc   = (const float*)d_in[3];
    const float* W_pred  = (const float*)d_in[4];
    const float* b_pred  = (const float*)d_in[5];
    const float* W_out   = (const float*)d_in[6];
    const float* b_out   = (const float*)d_in[7];
    float* out = (float*)d_out;

    void* p;
    cudaGetSymbolAddress(&p, g_enc);
    float* enc = (float*)p;
    cudaGetSymbolAddress(&p, g_pred);
    float* pred = (float*)p;

    proj_both_kernel<<<dim3(HH / 64, 25, 2), dim3(16, 16)>>>(
        enc_in, W_enc, b_enc, enc, pred_in, W_pred, b_pred, pred);

    cudaFuncSetAttribute(joint_mma_kernel,
                         cudaFuncAttributeMaxDynamicSharedMemorySize, JSMEM_TOT);
    joint_mma_kernel<<<dim3(MTOT / 128, VV / 256), 512, JSMEM_TOT>>>(
        W_out, b_out, out);
}

// round 15
// speedup vs baseline: 1.2754x; 1.2754x over previous
#include <cuda_runtime.h>
#include <cstdint>

// Problem constants
#define BB 8
#define TT 200
#define UU 100
#define EE 512
#define PP 640
#define HH 512
#define VV 1024
#define TUU (TT * UU)          // 20000
#define MTOT (BB * TUU)        // 160000

// Scratch (no cudaMalloc allowed)
__device__ float g_enc[BB * TT * HH];   // 1600 x 512
__device__ float g_pred[BB * UU * HH];  //  800 x 512

// ===========================================================================
// Helpers
// ===========================================================================
__device__ __forceinline__ uint32_t smem_u32(const void* p) {
    uint32_t a;
    asm("{ .reg .u64 t; cvta.to.shared.u64 t, %1; cvt.u32.u64 %0, t; }"
        : "=r"(a) : "l"(p));
    return a;
}

__device__ __forceinline__ unsigned f2tf32(float x) {
    unsigned r;
    asm("cvt.rna.tf32.f32 %0, %1;" : "=r"(r) : "f"(x));
    return r;
}

__device__ __forceinline__ void mma_tf32(float* c, const unsigned* a,
                                         unsigned b0, unsigned b1) {
    asm volatile(
        "mma.sync.aligned.m16n8k8.row.col.f32.tf32.tf32.f32 "
        "{%0,%1,%2,%3}, {%4,%5,%6,%7}, {%8,%9}, {%0,%1,%2,%3};\n"
        : "+f"(c[0]), "+f"(c[1]), "+f"(c[2]), "+f"(c[3])
        : "r"(a[0]), "r"(a[1]), "r"(a[2]), "r"(a[3]), "r"(b0), "r"(b1));
}

__device__ __forceinline__ void cp_async16(uint32_t dst, const void* src) {
    asm volatile(
        "{ .reg .u64 g; cvta.to.global.u64 g, %1;"
        "  cp.async.cg.shared.global [%0], [g], 16; }"
        :: "r"(dst), "l"(src) : "memory");
}
#define CP_COMMIT() asm volatile("cp.async.commit_group;" ::: "memory")
#define CP_WAIT0()  asm volatile("cp.async.wait_group 0;" ::: "memory")

// ===========================================================================
// Phase 1: both projections in one launch (z=0: enc, z=1: pred)
// (validated in R10 pass)
// ===========================================================================
__global__ __launch_bounds__(256) void proj_both_kernel(
    const float* __restrict__ encX, const float* __restrict__ Wenc,
    const float* __restrict__ benc, float* __restrict__ encY,
    const float* __restrict__ predX, const float* __restrict__ Wpred,
    const float* __restrict__ bpred, float* __restrict__ predY)
{
    const int z = blockIdx.z;
    const float* X = z ? predX : encX;
    const float* W = z ? Wpred : Wenc;
    const float* bias = z ? bpred : benc;
    float* Y = z ? predY : encY;
    const int M = z ? (BB * UU) : (BB * TT);
    const int K = z ? PP : EE;
    const int N = HH;

    const int mBase = blockIdx.y * 64;
    if (mBase >= M) return;
    const int nBase = blockIdx.x * 64;

    __shared__ float Xs[16][68];
    __shared__ float Ws[16][68];

    const int tx = threadIdx.x;
    const int ty = threadIdx.y;
    const int tid = ty * 16 + tx;
    const int lm = tid & 63;
    const int kq = (tid >> 6) * 4;

    float acc[4][4];
#pragma unroll
    for (int i = 0; i < 4; i++)
#pragma unroll
        for (int j = 0; j < 4; j++) acc[i][j] = 0.f;

    for (int k0 = 0; k0 < K; k0 += 16) {
        float4 xv = make_float4(0.f, 0.f, 0.f, 0.f);
        const int row = mBase + lm;
        if (row < M)
            xv = *(const float4*)(X + (size_t)row * K + k0 + kq);
        Xs[kq + 0][lm] = xv.x; Xs[kq + 1][lm] = xv.y;
        Xs[kq + 2][lm] = xv.z; Xs[kq + 3][lm] = xv.w;

        float4 wv = *(const float4*)(W + (size_t)(nBase + lm) * K + k0 + kq);
        Ws[kq + 0][lm] = wv.x; Ws[kq + 1][lm] = wv.y;
        Ws[kq + 2][lm] = wv.z; Ws[kq + 3][lm] = wv.w;

        __syncthreads();
#pragma unroll
        for (int kk = 0; kk < 16; kk++) {
            float4 a = *(const float4*)&Xs[kk][ty * 4];
            float4 b = *(const float4*)&Ws[kk][tx * 4];
            float av[4] = {a.x, a.y, a.z, a.w};
            float bv[4] = {b.x, b.y, b.z, b.w};
#pragma unroll
            for (int i = 0; i < 4; i++)
#pragma unroll
                for (int j = 0; j < 4; j++)
                    acc[i][j] = fmaf(av[i], bv[j], acc[i][j]);
        }
        __syncthreads();
    }

    float4 bb = *(const float4*)(bias + nBase + tx * 4);
    float bv[4] = {bb.x, bb.y, bb.z, bb.w};
#pragma unroll
    for (int i = 0; i < 4; i++) {
        const int row = mBase + ty * 4 + i;
        if (row < M) {
            float4 o;
            o.x = acc[i][0] + bv[0]; o.y = acc[i][1] + bv[1];
            o.z = acc[i][2] + bv[2]; o.w = acc[i][3] + bv[3];
            *(float4*)(Y + (size_t)row * N + nBase + tx * 4) = o;
        }
    }
}

// ===========================================================================
// Phase 2: fused joint GEMM — R5-verified addressing, occupancy 2.
//   CTA 64(M) x 256(N), 256 threads, K-chunk 32, warp tile 32x64.
//   Deltas vs R5 (each independently safe):
//     - B loaded via cp.async as raw fp32 (RZ-truncated by MMA; validated)
//     - A chunk software-pipelined through registers (LDG hidden behind MMA)
// ===========================================================================
#define SA 36  // smem row stride (words) for A [64 x 32]
#define SB 36  // smem row stride (words) for B [256 x 32]

__global__ __launch_bounds__(256, 2) void joint_mma_kernel(
    const float* __restrict__ Wout, const float* __restrict__ bout,
    float* __restrict__ out)
{
    __shared__ unsigned As[64 * SA];    //  9216 B
    __shared__ unsigned Bs[256 * SB];   // 36864 B
    __shared__ int encOff[64];
    __shared__ int predOff[64];

    const int tid = threadIdx.x;
    const int mBase = blockIdx.x * 64;
    const int vBase = blockIdx.y * 256;

    if (tid < 64) {
        const int gm = mBase + tid;
        const int b = gm / TUU;
        const int r = gm % TUU;
        const int t = r / UU;
        const int u = r % UU;
        encOff[tid] = (b * TT + t) * HH;
        predOff[tid] = (b * UU + u) * HH;
    }
    __syncthreads();

    const int lane = tid & 31;
    const int warp = tid >> 5;
    const int warpM = (warp & 1) * 32;      // 0 or 32
    const int warpN = (warp >> 1) * 64;     // 0,64,128,192
    const int gID = lane >> 2;              // 0..7
    const int t4 = lane & 3;                // 0..3

    // A-fill mapping: each thread covers 8 k of one m-row (R5-verified)
    const int am = tid >> 2;                // 0..63
    const int akq = (tid & 3) * 8;          // 0,8,16,24
    const float* encP = g_enc + encOff[am] + akq;
    const float* predP = g_pred + predOff[am] + akq;

    // B-fill mapping: 8 lanes per W_out row, 8 passes (R5-verified addresses)
    const int bn = tid >> 3;                // 0..31
    const int bkk = (tid & 7) * 4;          // 0..28
    const float* bsrc = Wout + (size_t)(vBase + bn) * HH + bkk;
    const uint32_t bDst0 = smem_u32(&Bs[bn * SB + bkk]);

    float acc[2][8][4];
#pragma unroll
    for (int mt = 0; mt < 2; mt++)
#pragma unroll
        for (int nt = 0; nt < 8; nt++)
#pragma unroll
            for (int i = 0; i < 4; i++) acc[mt][nt][i] = 0.f;

    // ---- prologue: prefetch chunk 0's A into registers ----
    float4 e0 = *(const float4*)(encP);
    float4 e1 = *(const float4*)(encP + 4);
    float4 p0 = *(const float4*)(predP);
    float4 p1 = *(const float4*)(predP + 4);

    for (int it = 0; it < 16; it++) {
        const int k0 = it * 32;

        // ---- store A chunk from regs: relu(enc+pred) -> tf32 (R5 layout) ----
        {
            uint4 v0, v1;
            v0.x = f2tf32(fmaxf(e0.x + p0.x, 0.f));
            v0.y = f2tf32(fmaxf(e0.y + p0.y, 0.f));
            v0.z = f2tf32(fmaxf(e0.z + p0.z, 0.f));
            v0.w = f2tf32(fmaxf(e0.w + p0.w, 0.f));
            v1.x = f2tf32(fmaxf(e1.x + p1.x, 0.f));
            v1.y = f2tf32(fmaxf(e1.y + p1.y, 0.f));
            v1.z = f2tf32(fmaxf(e1.z + p1.z, 0.f));
            v1.w = f2tf32(fmaxf(e1.w + p1.w, 0.f));
            *(uint4*)&As[am * SA + akq] = v0;
            *(uint4*)&As[am * SA + akq + 4] = v1;
        }

        // ---- B chunk via cp.async (raw fp32; same dst addresses as R5) ----
#pragma unroll
        for (int p = 0; p < 8; p++)
            cp_async16(bDst0 + (uint32_t)(p * 32 * SB * 4),
                       bsrc + k0 + (size_t)p * 32 * HH);
        CP_COMMIT();

        // ---- prefetch next chunk's A into regs (hidden behind MMA) ----
        if (it < 15) {
            e0 = *(const float4*)(encP + k0 + 32);
            e1 = *(const float4*)(encP + k0 + 36);
            p0 = *(const float4*)(predP + k0 + 32);
            p1 = *(const float4*)(predP + k0 + 36);
        }

        CP_WAIT0();
        __syncthreads();

        // ---- 4 x k8 MMA steps (R5-verified addressing, verbatim) ----
#pragma unroll
        for (int s = 0; s < 4; s++) {
            const int kk = s * 8;
            unsigned a[2][4];
#pragma unroll
            for (int mt = 0; mt < 2; mt++) {
                const int rb = (warpM + mt * 16 + gID) * SA + kk + t4;
                a[mt][0] = As[rb];
                a[mt][1] = As[rb + 8 * SA];
                a[mt][2] = As[rb + 4];
                a[mt][3] = As[rb + 8 * SA + 4];
            }
#pragma unroll
            for (int nt = 0; nt < 8; nt++) {
                const int nb = (warpN + nt * 8 + gID) * SB + kk + t4;
                const unsigned b0 = Bs[nb];
                const unsigned b1 = Bs[nb + 4];
                mma_tf32(acc[0][nt], a[0], b0, b1);
                mma_tf32(acc[1][nt], a[1], b0, b1);
            }
        }
        __syncthreads();
    }

    // ---- epilogue: (acc + b_out) * 0.1, fp32 out (R5 verbatim) ----
#pragma unroll
    for (int mt = 0; mt < 2; mt++) {
        const int row0 = mBase + warpM + mt * 16 + gID;
#pragma unroll
        for (int nt = 0; nt < 8; nt++) {
            const int v = vBase + warpN + nt * 8 + t4 * 2;
            const float bo0 = __ldg(bout + v);
            const float bo1 = __ldg(bout + v + 1);
            float2 r0, r1;
            r0.x = (acc[mt][nt][0] + bo0) * 0.1f;
            r0.y = (acc[mt][nt][1] + bo1) * 0.1f;
            r1.x = (acc[mt][nt][2] + bo0) * 0.1f;
            r1.y = (acc[mt][nt][3] + bo1) * 0.1f;
            *(float2*)(out + (size_t)row0 * VV + v) = r0;
            *(float2*)(out + (size_t)(row0 + 8) * VV + v) = r1;
        }
    }
}

// ===========================================================================
// Launch
// ===========================================================================
extern "C" void kernel_launch(void* const* d_in, const int* in_sizes, int n_in,
                              void* d_out, int out_size)
{
    (void)in_sizes; (void)n_in; (void)out_size;
    const float* enc_in  = (const float*)d_in[0];
    const float* pred_in = (const float*)d_in[1];
    const float* W_enc   = (const float*)d_in[2];
    const float* b_enc   = (const float*)d_in[3];
    const float* W_pred  = (const float*)d_in[4];
    const float* b_pred  = (const float*)d_in[5];
    const float* W_out   = (const float*)d_in[6];
    const float* b_out   = (const float*)d_in[7];
    float* out = (float*)d_out;

    void* p;
    cudaGetSymbolAddress(&p, g_enc);
    float* enc = (float*)p;
    cudaGetSymbolAddress(&p, g_pred);
    float* pred = (float*)p;

    proj_both_kernel<<<dim3(HH / 64, 25, 2), dim3(16, 16)>>>(
        enc_in, W_enc, b_enc, enc, pred_in, W_pred, b_pred, pred);

    // fused joint GEMM: 2500 x 4 CTAs of 256 threads, occupancy 2
    joint_mma_kernel<<<dim3(MTOT / 64, VV / 256), 256>>>(W_out, b_out, out);
}